// round 14
// baseline (speedup 1.0000x reference)
#include <cuda_runtime.h>
#include <cuda_bf16.h>
#include <math.h>

#define TT 512
#define BB 64
#define CC 256
#define HH 1024
#define RR (TT*BB)
#define BBHH (BB*HH)

#define NB_RNN 128
#define HSTR 1032                         // bf16 row stride (2064 B)
#define HS_BYTES (16*HSTR*2)              // one h buffer (hi or lo): 33024
#define RED_OFF (2*HS_BYTES)              // 66048
#define RNN2_SMEM (RED_OFF + 28*32*16)    // + red 14336 = 80384

typedef unsigned long long ull;
typedef unsigned int uint;

// ---------------- scratch ----------------
__device__ float g_xw[(size_t)TT*BB*HH];
__device__ float g_y0[(size_t)TT*BB*HH];
__device__ float g_y1[(size_t)TT*BB*HH];
// bf16 hi/lo activation arrays; slot 0 = initial h, slot t+1 = y[t]
__device__ __nv_bfloat16 g_y0h[(size_t)(TT+1)*BBHH];
__device__ __nv_bfloat16 g_y0l[(size_t)(TT+1)*BBHH];
__device__ __nv_bfloat16 g_y1h[(size_t)(TT+1)*BBHH];
__device__ __nv_bfloat16 g_y1l[(size_t)(TT+1)*BBHH];
// bf16 split scratch for GEMM inputs (x) and weights
__device__ __nv_bfloat16 g_ah[(size_t)RR*CC];
__device__ __nv_bfloat16 g_al[(size_t)RR*CC];
__device__ __nv_bfloat16 g_wh[(size_t)HH*HH];
__device__ __nv_bfloat16 g_wl[(size_t)HH*HH];

// -------- per-CTA monotonic flags: 4 domains x 32 CTAs, one 128B line each --
__device__ __align__(128) unsigned g_flag4[4*32];

__device__ __forceinline__ unsigned ld_relaxed(const unsigned* p) {
    unsigned v;
    asm volatile("ld.relaxed.gpu.global.u32 %0, [%1];" : "=r"(v) : "l"(p) : "memory");
    return v;
}

// flag barrier: publish own flag (release), poll all 32 in domain (acquire)
__device__ __forceinline__ void flag_sync(unsigned* flags, int cg, unsigned target) {
    __syncthreads();
    if (threadIdx.x == 0) {
        asm volatile("fence.acq_rel.gpu;" ::: "memory");   // release own stores
        asm volatile("st.relaxed.gpu.global.u32 [%0], %1;"
                     :: "l"(flags + cg), "r"(target) : "memory");
        for (;;) {
            uint ok = 1;
            #pragma unroll
            for (int q = 0; q < 8; q++) {
                uint4 v;
                asm volatile("ld.relaxed.gpu.global.v4.u32 {%0,%1,%2,%3}, [%4];"
                             : "=r"(v.x), "=r"(v.y), "=r"(v.z), "=r"(v.w)
                             : "l"(flags + q*4) : "memory");
                if ((int)(v.x - target) < 0 || (int)(v.y - target) < 0 ||
                    (int)(v.z - target) < 0 || (int)(v.w - target) < 0) ok = 0;
            }
            if (ok) break;
        }
        asm volatile("fence.acq_rel.gpu;" ::: "memory");   // acquire
    }
    __syncthreads();
}

// ---------------- bf16 split helpers ----------------
__device__ __forceinline__ uint packbf(float a, float b) {   // lo16=a, hi16=b
    uint r;
    asm("cvt.rn.bf16x2.f32 %0, %1, %2;" : "=r"(r) : "f"(b), "f"(a));
    return r;
}
__device__ __forceinline__ uint packlo(float a, float b, uint h) {
    float ha = __uint_as_float(h << 16);
    float hb = __uint_as_float(h & 0xFFFF0000u);
    return packbf(a - ha, b - hb);
}

// fp32 -> (bf16 hi, bf16 lo), 8 elements/thread
__global__ __launch_bounds__(256) void cvt_split_kernel(
    const float4* __restrict__ src, uint4* __restrict__ hi,
    uint4* __restrict__ lo, int n8)
{
    int i = blockIdx.x * 256 + threadIdx.x;
    if (i >= n8) return;
    float4 v0 = src[2*i], v1 = src[2*i + 1];
    uint h0 = packbf(v0.x, v0.y), h1 = packbf(v0.z, v0.w);
    uint h2 = packbf(v1.x, v1.y), h3 = packbf(v1.z, v1.w);
    uint l0 = packlo(v0.x, v0.y, h0), l1 = packlo(v0.z, v0.w, h1);
    uint l2 = packlo(v1.x, v1.y, h2), l3 = packlo(v1.z, v1.w, h3);
    hi[i] = make_uint4(h0, h1, h2, h3);
    lo[i] = make_uint4(l0, l1, l2, l3);
}

// ---------------- shared mma plumbing ----------------
__device__ __forceinline__ uint smem_u32(const void* p) {
    uint a;
    asm("{ .reg .u64 t; cvta.to.shared.u64 t, %1; cvt.u32.u64 %0, t; }"
        : "=r"(a) : "l"(p));
    return a;
}

#define LDSM4(r, addr) \
    asm volatile("ldmatrix.sync.aligned.m8n8.x4.shared.b16 {%0,%1,%2,%3}, [%4];" \
        : "=r"((r)[0]), "=r"((r)[1]), "=r"((r)[2]), "=r"((r)[3]) : "r"(addr))

#define MMA16816(d, a, b0, b1v) \
    asm volatile("mma.sync.aligned.m16n8k16.row.col.f32.bf16.bf16.f32 " \
        "{%0,%1,%2,%3}, {%4,%5,%6,%7}, {%8,%9}, {%0,%1,%2,%3};" \
        : "+f"((d)[0]), "+f"((d)[1]), "+f"((d)[2]), "+f"((d)[3]) \
        : "r"((a)[0]), "r"((a)[1]), "r"((a)[2]), "r"((a)[3]), "r"(b0), "r"(b1v))

#define STS128U(addr, a, b, c, d) \
    asm volatile("st.shared.v4.b32 [%0], {%1, %2, %3, %4};" \
                 :: "r"(addr), "r"(a), "r"(b), "r"(c), "r"(d) : "memory")

#define CPASYNC16(saddr, gptr) \
    asm volatile("cp.async.cg.shared.global [%0], [%1], 16;" \
                 :: "r"((uint)(saddr)), "l"(gptr) : "memory")
#define CPCOMMIT() asm volatile("cp.async.commit_group;" ::: "memory")
#define CPWAIT1()  asm volatile("cp.async.wait_group 1;" ::: "memory")
#define CPWAIT0()  asm volatile("cp.async.wait_group 0;" ::: "memory")

// ---------------- mma.sync bf16x3 GEMM, cp.async 3-stage (UNCHANGED) -------
#define GSTR 40
#define TBLK (128*GSTR)
#define TBLKB (TBLK*2)
#define NSTAGE 3
#define GEMM_SMEM (NSTAGE*4*TBLKB)     // 122880 B

__global__ __launch_bounds__(256) void mma_gemm_kernel(
    const __nv_bfloat16* __restrict__ Ah, const __nv_bfloat16* __restrict__ Al,
    const __nv_bfloat16* __restrict__ Wh, const __nv_bfloat16* __restrict__ Wl,
    const float* __restrict__ b1, const float* __restrict__ b2,
    float* __restrict__ out, int N, int K)
{
    extern __shared__ char gsm[];
    const uint sbase = smem_u32(gsm);
    const int tid  = threadIdx.x;
    const int warp = tid >> 5;
    const int lane = tid & 31;
    const int c0 = blockIdx.x * 128;
    const int r0 = blockIdx.y * 128;
    const int wm = warp >> 2;
    const int wn = warp & 3;

    const int lr = tid & 127;
    const __nv_bfloat16* gh0 = (tid < 128) ? (Ah + (size_t)(r0 + lr) * K)
                                           : (Wh + (size_t)(c0 + lr) * K);
    const __nv_bfloat16* gl0 = (tid < 128) ? (Al + (size_t)(r0 + lr) * K)
                                           : (Wl + (size_t)(c0 + lr) * K);
    const uint sdst_h = (tid < 128 ? 0u : 2u*TBLKB) + (uint)lr * (GSTR*2);

    const uint aoff = (((lane & 7) + ((lane >> 3) & 1) * 8) * GSTR
                       + (lane >> 4) * 8) * 2;
    const uint boff = (((lane & 7) + (lane >> 4) * 8) * GSTR
                       + ((lane >> 3) & 1) * 8) * 2;

    float acc[4][4][4];
    #pragma unroll
    for (int m = 0; m < 4; m++)
        #pragma unroll
        for (int n = 0; n < 4; n++)
            #pragma unroll
            for (int q = 0; q < 4; q++) acc[m][n][q] = 0.f;

    const int nk = K / 32;

    auto loadStageAsync = [&](int kt, int s) {
        const __nv_bfloat16* gh = gh0 + kt * 32;
        const __nv_bfloat16* gl = gl0 + kt * 32;
        uint bh = sbase + (uint)s * (4*TBLKB) + sdst_h;
        uint bl = bh + TBLKB;
        CPASYNC16(bh +  0, gh);
        CPASYNC16(bh + 16, gh + 8);
        CPASYNC16(bh + 32, gh + 16);
        CPASYNC16(bh + 48, gh + 24);
        CPASYNC16(bl +  0, gl);
        CPASYNC16(bl + 16, gl + 8);
        CPASYNC16(bl + 32, gl + 16);
        CPASYNC16(bl + 48, gl + 24);
        CPCOMMIT();
    };

    loadStageAsync(0, 0);
    loadStageAsync(1, 1);

    for (int kt = 0; kt < nk; kt++) {
        const int s = kt % NSTAGE;
        if (kt + 1 < nk) { CPWAIT1(); } else { CPWAIT0(); }
        __syncthreads();
        if (kt + 2 < nk) loadStageAsync(kt + 2, (kt + 2) % NSTAGE);

        const uint sb = sbase + (uint)s * (4*TBLKB);
        #pragma unroll
        for (int kb = 0; kb < 2; kb++) {
            const uint kbb = (uint)kb * 32;
            uint ah[4][4], al[4][4], bhf[2][4], blf[2][4];
            #pragma unroll
            for (int mt = 0; mt < 4; mt++) {
                uint ab = sb + ((uint)(wm*64 + mt*16) * GSTR) * 2 + kbb + aoff;
                LDSM4(ah[mt], ab);
                LDSM4(al[mt], ab + TBLKB);
            }
            #pragma unroll
            for (int nt2 = 0; nt2 < 2; nt2++) {
                uint bb = sb + 2u*TBLKB
                        + ((uint)(wn*32 + nt2*16) * GSTR) * 2 + kbb + boff;
                LDSM4(bhf[nt2], bb);
                LDSM4(blf[nt2], bb + TBLKB);
            }
            #pragma unroll
            for (int mt = 0; mt < 4; mt++)
                #pragma unroll
                for (int nt = 0; nt < 4; nt++) {
                    uint* bp = bhf[nt >> 1];
                    MMA16816(acc[mt][nt], ah[mt], bp[(nt & 1) * 2], bp[(nt & 1) * 2 + 1]);
                }
            #pragma unroll
            for (int mt = 0; mt < 4; mt++)
                #pragma unroll
                for (int nt = 0; nt < 4; nt++) {
                    uint* bp = blf[nt >> 1];
                    MMA16816(acc[mt][nt], ah[mt], bp[(nt & 1) * 2], bp[(nt & 1) * 2 + 1]);
                }
            #pragma unroll
            for (int mt = 0; mt < 4; mt++)
                #pragma unroll
                for (int nt = 0; nt < 4; nt++) {
                    uint* bp = bhf[nt >> 1];
                    MMA16816(acc[mt][nt], al[mt], bp[(nt & 1) * 2], bp[(nt & 1) * 2 + 1]);
                }
        }
    }

    const int rowb = r0 + wm*64 + (lane >> 2);
    const int colb = c0 + wn*32 + (lane & 3) * 2;
    #pragma unroll
    for (int nt = 0; nt < 4; nt++) {
        int col = colb + nt * 8;
        float bv0 = b1[col]     + (b2 ? b2[col]     : 0.f);
        float bv1 = b1[col + 1] + (b2 ? b2[col + 1] : 0.f);
        #pragma unroll
        for (int mt = 0; mt < 4; mt++) {
            int row = rowb + mt * 16;
            float2 o0 = make_float2(acc[mt][nt][0] + bv0, acc[mt][nt][1] + bv1);
            float2 o1 = make_float2(acc[mt][nt][2] + bv0, acc[mt][nt][3] + bv1);
            *(float2*)(out + (size_t)row * N + col)       = o0;
            *(float2*)(out + (size_t)(row + 8) * N + col) = o1;
        }
    }
}

// ------------- persistent recurrence, tensor-core + register-W -------------
// r13 core + (a) 3-way accumulator split (breaks the 24-MMA RAW chain),
// (b) flag-line barrier (one fewer serial L2 round-trip per step).
__global__ __launch_bounds__(1024) void rnn_mma_kernel(
    const float* __restrict__ xw,
    __nv_bfloat16* __restrict__ yh, __nv_bfloat16* __restrict__ yl,
    float* __restrict__ yfp, const float* __restrict__ Whh, int nsteps)
{
    extern __shared__ char smemc[];
    const uint hbase = smem_u32(smemc);
    float* redf = (float*)(smemc + RED_OFF);   // [28 warps][32 lanes][4]

    const int tid = threadIdx.x;
    const int bid = blockIdx.x;
    const int cg  = bid & 31;
    const int bg  = bid >> 5;
    const int c0  = cg * 32;
    const int warp = tid >> 5;
    const int lane = tid & 31;
    const int kg  = warp >> 2;       // k-split 0..7 (128 k each)
    const int nt  = warp & 3;        // n-tile 0..3 (8 cols each)

    unsigned* flags = &g_flag4[bg*32];
    unsigned base = ld_relaxed(flags + cg);   // all domain flags equal at launch

    // ---- one-time: W B-fragments into registers (bf16 hi/lo) ----
    const int nW = c0 + nt*8 + (lane >> 2);
    const int kW = kg*128 + 2*(lane & 3);
    uint whi0[8], whi1[8], wlo0[8], wlo1[8];
    #pragma unroll
    for (int kt = 0; kt < 8; kt++) {
        const float* wp = Whh + (size_t)nW * HH + kW + kt*16;
        float2 w0 = *(const float2*)(wp);
        float2 w1 = *(const float2*)(wp + 8);
        whi0[kt] = packbf(w0.x, w0.y); wlo0[kt] = packlo(w0.x, w0.y, whi0[kt]);
        whi1[kt] = packbf(w1.x, w1.y); wlo1[kt] = packlo(w1.x, w1.y, whi1[kt]);
    }

    // staging: thread -> 16 k of one batch row (hi + lo), via cp.async
    const int sb  = tid & 15;
    const int skc = tid >> 4;        // 0..63
    const uint sdst = hbase + (uint)sb * (HSTR*2) + (uint)skc * 32;

    // ldmatrix A offset
    const uint aoff = (uint)(((lane & 7) + ((lane >> 3) & 1) * 8) * (HSTR*2)
                             + (lane >> 4) * 16);

    // epilogue mapping (D-frag)
    const int erow = bg*16 + (lane >> 2);
    const int ecol = c0 + nt*8 + (lane & 3)*2;

    for (int t = 0; t < nsteps; t++) {
        // stage h (hi/lo bf16) from slot t  (issue ASAP after barrier)
        {
            const __nv_bfloat16* sh = yh + (size_t)t*BBHH
                                      + (size_t)(bg*16 + sb)*HH + skc*16;
            const __nv_bfloat16* sl = yl + (size_t)t*BBHH
                                      + (size_t)(bg*16 + sb)*HH + skc*16;
            CPASYNC16(sdst,      sh);
            CPASYNC16(sdst + 16, sh + 8);
            CPASYNC16(sdst + HS_BYTES,      sl);
            CPASYNC16(sdst + HS_BYTES + 16, sl + 8);
            CPCOMMIT();
        }

        // prefetch xw for epilogue (reducing warps only)
        size_t idx0 = ((size_t)t*BB + erow)*HH + ecol;
        float2 xw0, xw8;
        if (kg == 0) {
            xw0 = *(const float2*)&xw[idx0];
            xw8 = *(const float2*)&xw[idx0 + 8*HH];
        }

        CPWAIT0();
        __syncthreads();

        // 3 independent accumulator chains (8 MMAs each)
        float accA[4] = {0.f, 0.f, 0.f, 0.f};
        float accB[4] = {0.f, 0.f, 0.f, 0.f};
        float accC[4] = {0.f, 0.f, 0.f, 0.f};
        #pragma unroll
        for (int kt = 0; kt < 8; kt++) {
            uint ab = hbase + (uint)((kg*128 + kt*16) * 2) + aoff;
            uint Ah[4], Al[4];
            LDSM4(Ah, ab);
            LDSM4(Al, ab + HS_BYTES);
            MMA16816(accA, Ah, whi0[kt], whi1[kt]);   // Ah*Wh
            MMA16816(accB, Ah, wlo0[kt], wlo1[kt]);   // Ah*Wl
            MMA16816(accC, Al, whi0[kt], whi1[kt]);   // Al*Wh
        }
        float acc[4];
        #pragma unroll
        for (int q = 0; q < 4; q++) acc[q] = accA[q] + (accB[q] + accC[q]);

        // k-split reduction via smem (warps kg>0 store; kg==0 reduces)
        if (kg) *(float4*)(redf + (warp - 4)*128 + lane*4) = *(float4*)acc;
        __syncthreads();
        if (kg == 0) {
            #pragma unroll
            for (int k = 1; k < 8; k++) {
                float4 o = *(float4*)(redf + (k*4 + nt - 4)*128 + lane*4);
                acc[0] += o.x; acc[1] += o.y; acc[2] += o.z; acc[3] += o.w;
            }
            float t0 = tanhf(xw0.x + acc[0]);
            float t1 = tanhf(xw0.y + acc[1]);
            float t2 = tanhf(xw8.x + acc[2]);
            float t3 = tanhf(xw8.y + acc[3]);
            uint h01 = packbf(t0, t1), l01 = packlo(t0, t1, h01);
            uint h23 = packbf(t2, t3), l23 = packlo(t2, t3, h23);
            size_t o0 = idx0 + BBHH;          // slot t+1
            *(uint*)&yh[o0]          = h01;
            *(uint*)&yl[o0]          = l01;
            *(uint*)&yh[o0 + 8*HH]   = h23;
            *(uint*)&yl[o0 + 8*HH]   = l23;
            if (t == nsteps - 1) {
                *(float2*)&yfp[idx0]          = make_float2(t0, t1);
                *(float2*)&yfp[idx0 + 8*HH]   = make_float2(t2, t3);
            }
        }

        flag_sync(flags, cg, base + (unsigned)t + 1u);
    }
}

// ------------- hidden-state gather ----------------
__global__ void gather_hidden_kernel(float* __restrict__ out_hidden)
{
    int i = blockIdx.x * blockDim.x + threadIdx.x;
    const float* src = (i < BBHH)
        ? (g_y0 + (size_t)(TT-1)*BBHH + i)
        : (g_y1 + (size_t)(TT-1)*BBHH + (i - BBHH));
    out_hidden[i] = *src;
}

extern "C" void kernel_launch(void* const* d_in, const int* in_sizes, int n_in,
                              void* d_out, int out_size) {
    const float* x     = (const float*)d_in[0];
    const float* h0    = (const float*)d_in[1];
    const float* w_ih0 = (const float*)d_in[2];
    const float* w_hh0 = (const float*)d_in[3];
    const float* b_ih0 = (const float*)d_in[4];
    const float* b_hh0 = (const float*)d_in[5];
    const float* w_ih1 = (const float*)d_in[6];
    const float* w_hh1 = (const float*)d_in[7];
    const float* b_ih1 = (const float*)d_in[8];
    const float* b_hh1 = (const float*)d_in[9];
    const float* w_dec = (const float*)d_in[10];
    const float* b_dec = (const float*)d_in[11];
    float* out = (float*)d_out;

    cudaFuncSetAttribute(rnn_mma_kernel,
                         cudaFuncAttributeMaxDynamicSharedMemorySize, RNN2_SMEM);
    cudaFuncSetAttribute(mma_gemm_kernel,
                         cudaFuncAttributeMaxDynamicSharedMemorySize, GEMM_SMEM);

    float* xw;  cudaGetSymbolAddress((void**)&xw,  g_xw);
    float* y0;  cudaGetSymbolAddress((void**)&y0,  g_y0);
    float* y1;  cudaGetSymbolAddress((void**)&y1,  g_y1);
    __nv_bfloat16 *ah, *al, *wh, *wl, *y0h, *y0l, *y1h, *y1l;
    cudaGetSymbolAddress((void**)&ah,  g_ah);
    cudaGetSymbolAddress((void**)&al,  g_al);
    cudaGetSymbolAddress((void**)&wh,  g_wh);
    cudaGetSymbolAddress((void**)&wl,  g_wl);
    cudaGetSymbolAddress((void**)&y0h, g_y0h);
    cudaGetSymbolAddress((void**)&y0l, g_y0l);
    cudaGetSymbolAddress((void**)&y1h, g_y1h);
    cudaGetSymbolAddress((void**)&y1l, g_y1l);

    // 0) split x, w_ih0, and both h0 slices (h0 -> slot 0 of yh/yl arrays)
    cvt_split_kernel<<<RR*CC/8/256, 256>>>((const float4*)x, (uint4*)ah, (uint4*)al, RR*CC/8);
    cvt_split_kernel<<<HH*CC/8/256, 256>>>((const float4*)w_ih0, (uint4*)wh, (uint4*)wl, HH*CC/8);
    cvt_split_kernel<<<BBHH/8/256, 256>>>((const float4*)h0, (uint4*)y0h, (uint4*)y0l, BBHH/8);
    cvt_split_kernel<<<BBHH/8/256, 256>>>((const float4*)(h0 + BBHH), (uint4*)y1h, (uint4*)y1l, BBHH/8);

    // 1) layer-0 input projection: xw = x @ w_ih0^T + b_ih0 + b_hh0
    {
        dim3 grid(HH/128, RR/128);
        mma_gemm_kernel<<<grid, 256, GEMM_SMEM>>>(ah, al, wh, wl, b_ih0, b_hh0, xw, HH, CC);
    }
    // 2) layer-0 recurrence
    rnn_mma_kernel<<<NB_RNN, 1024, RNN2_SMEM>>>(xw, y0h, y0l, y0, w_hh0, TT);
    // 3) layer-1 input projection (A = y0 hi/lo slots 1..512 directly)
    cvt_split_kernel<<<HH*HH/8/256, 256>>>((const float4*)w_ih1, (uint4*)wh, (uint4*)wl, HH*HH/8);
    {
        dim3 grid(HH/128, RR/128);
        mma_gemm_kernel<<<grid, 256, GEMM_SMEM>>>(y0h + BBHH, y0l + BBHH, wh, wl,
                                                  b_ih1, b_hh1, xw, HH, HH);
    }
    // 4) layer-1 recurrence
    rnn_mma_kernel<<<NB_RNN, 1024, RNN2_SMEM>>>(xw, y1h, y1l, y1, w_hh1, TT);
    // 5) decoder (A = y1 hi/lo slots 1..512)
    cvt_split_kernel<<<CC*HH/8/256, 256>>>((const float4*)w_dec, (uint4*)wh, (uint4*)wl, CC*HH/8);
    {
        dim3 grid(CC/128, RR/128);
        mma_gemm_kernel<<<grid, 256, GEMM_SMEM>>>(y1h + BBHH, y1l + BBHH, wh, wl,
                                                  b_dec, nullptr, out, CC, HH);
    }
    // 6) hidden states appended after decoded
    gather_hidden_kernel<<<(2*BBHH)/256, 256>>>(out + (size_t)TT*BB*CC);
}

// round 15
// speedup vs baseline: 1.9092x; 1.9092x over previous
#include <cuda_runtime.h>
#include <cuda_bf16.h>
#include <math.h>

#define TT 512
#define BB 64
#define CC 256
#define HH 1024
#define RR (TT*BB)
#define BBHH (BB*HH)

#define NB_RNN 128
#define HSTR 1032                         // bf16 row stride (2064 B)
#define HS_BYTES (16*HSTR*2)              // one h buffer (hi or lo): 33024
#define RED_OFF (2*HS_BYTES)              // 66048
#define RNN2_SMEM (RED_OFF + 28*32*16)    // + red 14336 = 80384

typedef unsigned long long ull;
typedef unsigned int uint;

// ---------------- scratch ----------------
__device__ float g_xw[(size_t)TT*BB*HH];
__device__ float g_y0[(size_t)TT*BB*HH];
__device__ float g_y1[(size_t)TT*BB*HH];
// bf16 hi/lo activation arrays; slot 0 = initial h, slot t+1 = y[t]
__device__ __nv_bfloat16 g_y0h[(size_t)(TT+1)*BBHH];
__device__ __nv_bfloat16 g_y0l[(size_t)(TT+1)*BBHH];
__device__ __nv_bfloat16 g_y1h[(size_t)(TT+1)*BBHH];
__device__ __nv_bfloat16 g_y1l[(size_t)(TT+1)*BBHH];
// bf16 split scratch for GEMM inputs (x) and weights
__device__ __nv_bfloat16 g_ah[(size_t)RR*CC];
__device__ __nv_bfloat16 g_al[(size_t)RR*CC];
__device__ __nv_bfloat16 g_wh[(size_t)HH*HH];
__device__ __nv_bfloat16 g_wl[(size_t)HH*HH];

// -------- per-batch-group grid barrier (monotonic, 4 domains of 32 CTAs) ---
__device__ unsigned g_cnt4[4*64];
__device__ unsigned g_gen4[4*64];

__device__ __forceinline__ unsigned ld_relaxed(const unsigned* p) {
    unsigned v;
    asm volatile("ld.relaxed.gpu.global.u32 %0, [%1];" : "=r"(v) : "l"(p) : "memory");
    return v;
}

__device__ __forceinline__ void group_sync(unsigned* cnt, unsigned* gen,
                                           unsigned target) {
    __syncthreads();
    if (threadIdx.x == 0) {
        unsigned old;
        asm volatile("atom.acq_rel.gpu.global.add.u32 %0, [%1], 1;"
                     : "=r"(old) : "l"(cnt) : "memory");
        if (old + 1u == 32u * target) {
            asm volatile("st.release.gpu.global.u32 [%0], %1;"
                         :: "l"(gen), "r"(target) : "memory");
        }
        unsigned v;
        do {
            asm volatile("ld.acquire.gpu.global.u32 %0, [%1];"
                         : "=r"(v) : "l"(gen) : "memory");
        } while ((int)(v - target) < 0);
    }
    __syncthreads();
}

// ---------------- bf16 split helpers ----------------
__device__ __forceinline__ uint packbf(float a, float b) {   // lo16=a, hi16=b
    uint r;
    asm("cvt.rn.bf16x2.f32 %0, %1, %2;" : "=r"(r) : "f"(b), "f"(a));
    return r;
}
__device__ __forceinline__ uint packlo(float a, float b, uint h) {
    float ha = __uint_as_float(h << 16);
    float hb = __uint_as_float(h & 0xFFFF0000u);
    return packbf(a - ha, b - hb);
}

// fp32 -> (bf16 hi, bf16 lo), 8 elements/thread
__global__ __launch_bounds__(256) void cvt_split_kernel(
    const float4* __restrict__ src, uint4* __restrict__ hi,
    uint4* __restrict__ lo, int n8)
{
    int i = blockIdx.x * 256 + threadIdx.x;
    if (i >= n8) return;
    float4 v0 = src[2*i], v1 = src[2*i + 1];
    uint h0 = packbf(v0.x, v0.y), h1 = packbf(v0.z, v0.w);
    uint h2 = packbf(v1.x, v1.y), h3 = packbf(v1.z, v1.w);
    uint l0 = packlo(v0.x, v0.y, h0), l1 = packlo(v0.z, v0.w, h1);
    uint l2 = packlo(v1.x, v1.y, h2), l3 = packlo(v1.z, v1.w, h3);
    hi[i] = make_uint4(h0, h1, h2, h3);
    lo[i] = make_uint4(l0, l1, l2, l3);
}

// ---------------- shared mma plumbing ----------------
__device__ __forceinline__ uint smem_u32(const void* p) {
    uint a;
    asm("{ .reg .u64 t; cvta.to.shared.u64 t, %1; cvt.u32.u64 %0, t; }"
        : "=r"(a) : "l"(p));
    return a;
}

#define LDSM4(r, addr) \
    asm volatile("ldmatrix.sync.aligned.m8n8.x4.shared.b16 {%0,%1,%2,%3}, [%4];" \
        : "=r"((r)[0]), "=r"((r)[1]), "=r"((r)[2]), "=r"((r)[3]) : "r"(addr))

#define MMA16816(d, a, b0, b1v) \
    asm volatile("mma.sync.aligned.m16n8k16.row.col.f32.bf16.bf16.f32 " \
        "{%0,%1,%2,%3}, {%4,%5,%6,%7}, {%8,%9}, {%0,%1,%2,%3};" \
        : "+f"((d)[0]), "+f"((d)[1]), "+f"((d)[2]), "+f"((d)[3]) \
        : "r"((a)[0]), "r"((a)[1]), "r"((a)[2]), "r"((a)[3]), "r"(b0), "r"(b1v))

#define STS128U(addr, a, b, c, d) \
    asm volatile("st.shared.v4.b32 [%0], {%1, %2, %3, %4};" \
                 :: "r"(addr), "r"(a), "r"(b), "r"(c), "r"(d) : "memory")

#define CPASYNC16(saddr, gptr) \
    asm volatile("cp.async.cg.shared.global [%0], [%1], 16;" \
                 :: "r"((uint)(saddr)), "l"(gptr) : "memory")
#define CPCOMMIT() asm volatile("cp.async.commit_group;" ::: "memory")
#define CPWAIT1()  asm volatile("cp.async.wait_group 1;" ::: "memory")
#define CPWAIT0()  asm volatile("cp.async.wait_group 0;" ::: "memory")

// ---------------- mma.sync bf16x3 GEMM, cp.async 3-stage (UNCHANGED) -------
#define GSTR 40
#define TBLK (128*GSTR)
#define TBLKB (TBLK*2)
#define NSTAGE 3
#define GEMM_SMEM (NSTAGE*4*TBLKB)     // 122880 B

__global__ __launch_bounds__(256) void mma_gemm_kernel(
    const __nv_bfloat16* __restrict__ Ah, const __nv_bfloat16* __restrict__ Al,
    const __nv_bfloat16* __restrict__ Wh, const __nv_bfloat16* __restrict__ Wl,
    const float* __restrict__ b1, const float* __restrict__ b2,
    float* __restrict__ out, int N, int K)
{
    extern __shared__ char gsm[];
    const uint sbase = smem_u32(gsm);
    const int tid  = threadIdx.x;
    const int warp = tid >> 5;
    const int lane = tid & 31;
    const int c0 = blockIdx.x * 128;
    const int r0 = blockIdx.y * 128;
    const int wm = warp >> 2;
    const int wn = warp & 3;

    const int lr = tid & 127;
    const __nv_bfloat16* gh0 = (tid < 128) ? (Ah + (size_t)(r0 + lr) * K)
                                           : (Wh + (size_t)(c0 + lr) * K);
    const __nv_bfloat16* gl0 = (tid < 128) ? (Al + (size_t)(r0 + lr) * K)
                                           : (Wl + (size_t)(c0 + lr) * K);
    const uint sdst_h = (tid < 128 ? 0u : 2u*TBLKB) + (uint)lr * (GSTR*2);

    const uint aoff = (((lane & 7) + ((lane >> 3) & 1) * 8) * GSTR
                       + (lane >> 4) * 8) * 2;
    const uint boff = (((lane & 7) + (lane >> 4) * 8) * GSTR
                       + ((lane >> 3) & 1) * 8) * 2;

    float acc[4][4][4];
    #pragma unroll
    for (int m = 0; m < 4; m++)
        #pragma unroll
        for (int n = 0; n < 4; n++)
            #pragma unroll
            for (int q = 0; q < 4; q++) acc[m][n][q] = 0.f;

    const int nk = K / 32;

    auto loadStageAsync = [&](int kt, int s) {
        const __nv_bfloat16* gh = gh0 + kt * 32;
        const __nv_bfloat16* gl = gl0 + kt * 32;
        uint bh = sbase + (uint)s * (4*TBLKB) + sdst_h;
        uint bl = bh + TBLKB;
        CPASYNC16(bh +  0, gh);
        CPASYNC16(bh + 16, gh + 8);
        CPASYNC16(bh + 32, gh + 16);
        CPASYNC16(bh + 48, gh + 24);
        CPASYNC16(bl +  0, gl);
        CPASYNC16(bl + 16, gl + 8);
        CPASYNC16(bl + 32, gl + 16);
        CPASYNC16(bl + 48, gl + 24);
        CPCOMMIT();
    };

    loadStageAsync(0, 0);
    loadStageAsync(1, 1);

    for (int kt = 0; kt < nk; kt++) {
        const int s = kt % NSTAGE;
        if (kt + 1 < nk) { CPWAIT1(); } else { CPWAIT0(); }
        __syncthreads();
        if (kt + 2 < nk) loadStageAsync(kt + 2, (kt + 2) % NSTAGE);

        const uint sb = sbase + (uint)s * (4*TBLKB);
        #pragma unroll
        for (int kb = 0; kb < 2; kb++) {
            const uint kbb = (uint)kb * 32;
            uint ah[4][4], al[4][4], bhf[2][4], blf[2][4];
            #pragma unroll
            for (int mt = 0; mt < 4; mt++) {
                uint ab = sb + ((uint)(wm*64 + mt*16) * GSTR) * 2 + kbb + aoff;
                LDSM4(ah[mt], ab);
                LDSM4(al[mt], ab + TBLKB);
            }
            #pragma unroll
            for (int nt2 = 0; nt2 < 2; nt2++) {
                uint bb = sb + 2u*TBLKB
                        + ((uint)(wn*32 + nt2*16) * GSTR) * 2 + kbb + boff;
                LDSM4(bhf[nt2], bb);
                LDSM4(blf[nt2], bb + TBLKB);
            }
            #pragma unroll
            for (int mt = 0; mt < 4; mt++)
                #pragma unroll
                for (int nt = 0; nt < 4; nt++) {
                    uint* bp = bhf[nt >> 1];
                    MMA16816(acc[mt][nt], ah[mt], bp[(nt & 1) * 2], bp[(nt & 1) * 2 + 1]);
                }
            #pragma unroll
            for (int mt = 0; mt < 4; mt++)
                #pragma unroll
                for (int nt = 0; nt < 4; nt++) {
                    uint* bp = blf[nt >> 1];
                    MMA16816(acc[mt][nt], ah[mt], bp[(nt & 1) * 2], bp[(nt & 1) * 2 + 1]);
                }
            #pragma unroll
            for (int mt = 0; mt < 4; mt++)
                #pragma unroll
                for (int nt = 0; nt < 4; nt++) {
                    uint* bp = bhf[nt >> 1];
                    MMA16816(acc[mt][nt], al[mt], bp[(nt & 1) * 2], bp[(nt & 1) * 2 + 1]);
                }
        }
    }

    const int rowb = r0 + wm*64 + (lane >> 2);
    const int colb = c0 + wn*32 + (lane & 3) * 2;
    #pragma unroll
    for (int nt = 0; nt < 4; nt++) {
        int col = colb + nt * 8;
        float bv0 = b1[col]     + (b2 ? b2[col]     : 0.f);
        float bv1 = b1[col + 1] + (b2 ? b2[col + 1] : 0.f);
        #pragma unroll
        for (int mt = 0; mt < 4; mt++) {
            int row = rowb + mt * 16;
            float2 o0 = make_float2(acc[mt][nt][0] + bv0, acc[mt][nt][1] + bv1);
            float2 o1 = make_float2(acc[mt][nt][2] + bv0, acc[mt][nt][3] + bv1);
            *(float2*)(out + (size_t)row * N + col)       = o0;
            *(float2*)(out + (size_t)(row + 8) * N + col) = o1;
        }
    }
}

// ------------- persistent recurrence, tensor-core + register-W -------------
// r13 kernel + 3-way accumulator split ONLY (r13's proven atomic barrier).
__global__ __launch_bounds__(1024) void rnn_mma_kernel(
    const float* __restrict__ xw,
    __nv_bfloat16* __restrict__ yh, __nv_bfloat16* __restrict__ yl,
    float* __restrict__ yfp, const float* __restrict__ Whh, int nsteps)
{
    extern __shared__ char smemc[];
    const uint hbase = smem_u32(smemc);
    float* redf = (float*)(smemc + RED_OFF);   // [28 warps][32 lanes][4]

    const int tid = threadIdx.x;
    const int bid = blockIdx.x;
    const int cg  = bid & 31;
    const int bg  = bid >> 5;
    const int c0  = cg * 32;
    const int warp = tid >> 5;
    const int lane = tid & 31;
    const int kg  = warp >> 2;       // k-split 0..7 (128 k each)
    const int nt  = warp & 3;        // n-tile 0..3 (8 cols each)

    unsigned* cnt = &g_cnt4[bg*64];
    unsigned* gen = &g_gen4[bg*64];
    unsigned gen0 = ld_relaxed(gen);

    // ---- one-time: W B-fragments into registers (bf16 hi/lo) ----
    const int nW = c0 + nt*8 + (lane >> 2);
    const int kW = kg*128 + 2*(lane & 3);
    uint whi0[8], whi1[8], wlo0[8], wlo1[8];
    #pragma unroll
    for (int kt = 0; kt < 8; kt++) {
        const float* wp = Whh + (size_t)nW * HH + kW + kt*16;
        float2 w0 = *(const float2*)(wp);
        float2 w1 = *(const float2*)(wp + 8);
        whi0[kt] = packbf(w0.x, w0.y); wlo0[kt] = packlo(w0.x, w0.y, whi0[kt]);
        whi1[kt] = packbf(w1.x, w1.y); wlo1[kt] = packlo(w1.x, w1.y, whi1[kt]);
    }

    // staging: thread -> 16 k of one batch row (hi + lo), via cp.async
    const int sb  = tid & 15;
    const int skc = tid >> 4;        // 0..63
    const uint sdst = hbase + (uint)sb * (HSTR*2) + (uint)skc * 32;

    // ldmatrix A offset
    const uint aoff = (uint)(((lane & 7) + ((lane >> 3) & 1) * 8) * (HSTR*2)
                             + (lane >> 4) * 16);

    // epilogue mapping (D-frag)
    const int erow = bg*16 + (lane >> 2);
    const int ecol = c0 + nt*8 + (lane & 3)*2;

    for (int t = 0; t < nsteps; t++) {
        // stage h (hi/lo bf16) from slot t  (issue ASAP after barrier)
        {
            const __nv_bfloat16* sh = yh + (size_t)t*BBHH
                                      + (size_t)(bg*16 + sb)*HH + skc*16;
            const __nv_bfloat16* sl = yl + (size_t)t*BBHH
                                      + (size_t)(bg*16 + sb)*HH + skc*16;
            CPASYNC16(sdst,      sh);
            CPASYNC16(sdst + 16, sh + 8);
            CPASYNC16(sdst + HS_BYTES,      sl);
            CPASYNC16(sdst + HS_BYTES + 16, sl + 8);
            CPCOMMIT();
        }

        // prefetch xw for epilogue (reducing warps only)
        size_t idx0 = ((size_t)t*BB + erow)*HH + ecol;
        float2 xw0, xw8;
        if (kg == 0) {
            xw0 = *(const float2*)&xw[idx0];
            xw8 = *(const float2*)&xw[idx0 + 8*HH];
        }

        CPWAIT0();
        __syncthreads();

        // 3 independent accumulator chains (8 MMAs each)
        float accA[4] = {0.f, 0.f, 0.f, 0.f};
        float accB[4] = {0.f, 0.f, 0.f, 0.f};
        float accC[4] = {0.f, 0.f, 0.f, 0.f};
        #pragma unroll
        for (int kt = 0; kt < 8; kt++) {
            uint ab = hbase + (uint)((kg*128 + kt*16) * 2) + aoff;
            uint Ah[4], Al[4];
            LDSM4(Ah, ab);
            LDSM4(Al, ab + HS_BYTES);
            MMA16816(accA, Ah, whi0[kt], whi1[kt]);   // Ah*Wh
            MMA16816(accB, Ah, wlo0[kt], wlo1[kt]);   // Ah*Wl
            MMA16816(accC, Al, whi0[kt], whi1[kt]);   // Al*Wh
        }
        float acc[4];
        #pragma unroll
        for (int q = 0; q < 4; q++) acc[q] = accA[q] + (accB[q] + accC[q]);

        // k-split reduction via smem (warps kg>0 store; kg==0 reduces)
        if (kg) *(float4*)(redf + (warp - 4)*128 + lane*4) = *(float4*)acc;
        __syncthreads();
        if (kg == 0) {
            #pragma unroll
            for (int k = 1; k < 8; k++) {
                float4 o = *(float4*)(redf + (k*4 + nt - 4)*128 + lane*4);
                acc[0] += o.x; acc[1] += o.y; acc[2] += o.z; acc[3] += o.w;
            }
            float t0 = tanhf(xw0.x + acc[0]);
            float t1 = tanhf(xw0.y + acc[1]);
            float t2 = tanhf(xw8.x + acc[2]);
            float t3 = tanhf(xw8.y + acc[3]);
            uint h01 = packbf(t0, t1), l01 = packlo(t0, t1, h01);
            uint h23 = packbf(t2, t3), l23 = packlo(t2, t3, h23);
            size_t o0 = idx0 + BBHH;          // slot t+1
            *(uint*)&yh[o0]          = h01;
            *(uint*)&yl[o0]          = l01;
            *(uint*)&yh[o0 + 8*HH]   = h23;
            *(uint*)&yl[o0 + 8*HH]   = l23;
            if (t == nsteps - 1) {
                *(float2*)&yfp[idx0]          = make_float2(t0, t1);
                *(float2*)&yfp[idx0 + 8*HH]   = make_float2(t2, t3);
            }
        }

        group_sync(cnt, gen, gen0 + (unsigned)t + 1u);
    }
}

// ------------- hidden-state gather ----------------
__global__ void gather_hidden_kernel(float* __restrict__ out_hidden)
{
    int i = blockIdx.x * blockDim.x + threadIdx.x;
    const float* src = (i < BBHH)
        ? (g_y0 + (size_t)(TT-1)*BBHH + i)
        : (g_y1 + (size_t)(TT-1)*BBHH + (i - BBHH));
    out_hidden[i] = *src;
}

extern "C" void kernel_launch(void* const* d_in, const int* in_sizes, int n_in,
                              void* d_out, int out_size) {
    const float* x     = (const float*)d_in[0];
    const float* h0    = (const float*)d_in[1];
    const float* w_ih0 = (const float*)d_in[2];
    const float* w_hh0 = (const float*)d_in[3];
    const float* b_ih0 = (const float*)d_in[4];
    const float* b_hh0 = (const float*)d_in[5];
    const float* w_ih1 = (const float*)d_in[6];
    const float* w_hh1 = (const float*)d_in[7];
    const float* b_ih1 = (const float*)d_in[8];
    const float* b_hh1 = (const float*)d_in[9];
    const float* w_dec = (const float*)d_in[10];
    const float* b_dec = (const float*)d_in[11];
    float* out = (float*)d_out;

    cudaFuncSetAttribute(rnn_mma_kernel,
                         cudaFuncAttributeMaxDynamicSharedMemorySize, RNN2_SMEM);
    cudaFuncSetAttribute(mma_gemm_kernel,
                         cudaFuncAttributeMaxDynamicSharedMemorySize, GEMM_SMEM);

    float* xw;  cudaGetSymbolAddress((void**)&xw,  g_xw);
    float* y0;  cudaGetSymbolAddress((void**)&y0,  g_y0);
    float* y1;  cudaGetSymbolAddress((void**)&y1,  g_y1);
    __nv_bfloat16 *ah, *al, *wh, *wl, *y0h, *y0l, *y1h, *y1l;
    cudaGetSymbolAddress((void**)&ah,  g_ah);
    cudaGetSymbolAddress((void**)&al,  g_al);
    cudaGetSymbolAddress((void**)&wh,  g_wh);
    cudaGetSymbolAddress((void**)&wl,  g_wl);
    cudaGetSymbolAddress((void**)&y0h, g_y0h);
    cudaGetSymbolAddress((void**)&y0l, g_y0l);
    cudaGetSymbolAddress((void**)&y1h, g_y1h);
    cudaGetSymbolAddress((void**)&y1l, g_y1l);

    // 0) split x, w_ih0, and both h0 slices (h0 -> slot 0 of yh/yl arrays)
    cvt_split_kernel<<<RR*CC/8/256, 256>>>((const float4*)x, (uint4*)ah, (uint4*)al, RR*CC/8);
    cvt_split_kernel<<<HH*CC/8/256, 256>>>((const float4*)w_ih0, (uint4*)wh, (uint4*)wl, HH*CC/8);
    cvt_split_kernel<<<BBHH/8/256, 256>>>((const float4*)h0, (uint4*)y0h, (uint4*)y0l, BBHH/8);
    cvt_split_kernel<<<BBHH/8/256, 256>>>((const float4*)(h0 + BBHH), (uint4*)y1h, (uint4*)y1l, BBHH/8);

    // 1) layer-0 input projection: xw = x @ w_ih0^T + b_ih0 + b_hh0
    {
        dim3 grid(HH/128, RR/128);
        mma_gemm_kernel<<<grid, 256, GEMM_SMEM>>>(ah, al, wh, wl, b_ih0, b_hh0, xw, HH, CC);
    }
    // 2) layer-0 recurrence
    rnn_mma_kernel<<<NB_RNN, 1024, RNN2_SMEM>>>(xw, y0h, y0l, y0, w_hh0, TT);
    // 3) layer-1 input projection (A = y0 hi/lo slots 1..512 directly)
    cvt_split_kernel<<<HH*HH/8/256, 256>>>((const float4*)w_ih1, (uint4*)wh, (uint4*)wl, HH*HH/8);
    {
        dim3 grid(HH/128, RR/128);
        mma_gemm_kernel<<<grid, 256, GEMM_SMEM>>>(y0h + BBHH, y0l + BBHH, wh, wl,
                                                  b_ih1, b_hh1, xw, HH, HH);
    }
    // 4) layer-1 recurrence
    rnn_mma_kernel<<<NB_RNN, 1024, RNN2_SMEM>>>(xw, y1h, y1l, y1, w_hh1, TT);
    // 5) decoder (A = y1 hi/lo slots 1..512)
    cvt_split_kernel<<<CC*HH/8/256, 256>>>((const float4*)w_dec, (uint4*)wh, (uint4*)wl, CC*HH/8);
    {
        dim3 grid(CC/128, RR/128);
        mma_gemm_kernel<<<grid, 256, GEMM_SMEM>>>(y1h + BBHH, y1l + BBHH, wh, wl,
                                                  b_dec, nullptr, out, CC, HH);
    }
    // 6) hidden states appended after decoded
    gather_hidden_kernel<<<(2*BBHH)/256, 256>>>(out + (size_t)TT*BB*CC);
}

// round 16
// speedup vs baseline: 2.0349x; 1.0658x over previous
#include <cuda_runtime.h>
#include <cuda_bf16.h>
#include <math.h>

#define TT 512
#define BB 64
#define CC 256
#define HH 1024
#define RR (TT*BB)
#define BBHH (BB*HH)

#define NB_RNN 128
#define HSTR 1032                         // bf16 row stride (2064 B)
#define HS_BYTES (16*HSTR*2)              // one h buffer (hi or lo): 33024
#define RED_OFF (2*HS_BYTES)              // 66048
#define RNN2_SMEM (RED_OFF + 28*32*16)    // + red 14336 = 80384

typedef unsigned long long ull;
typedef unsigned int uint;

// ---------------- scratch ----------------
__device__ float g_xw[(size_t)TT*BB*HH];
__device__ float g_y0[(size_t)TT*BB*HH];
__device__ float g_y1[(size_t)TT*BB*HH];
// bf16 hi/lo activation arrays; slot 0 = initial h, slot t+1 = y[t]
__device__ __nv_bfloat16 g_y0h[(size_t)(TT+1)*BBHH];
__device__ __nv_bfloat16 g_y0l[(size_t)(TT+1)*BBHH];
__device__ __nv_bfloat16 g_y1h[(size_t)(TT+1)*BBHH];
__device__ __nv_bfloat16 g_y1l[(size_t)(TT+1)*BBHH];
// bf16 split scratch for GEMM inputs (x) and weights
__device__ __nv_bfloat16 g_ah[(size_t)RR*CC];
__device__ __nv_bfloat16 g_al[(size_t)RR*CC];
__device__ __nv_bfloat16 g_wh[(size_t)HH*HH];
__device__ __nv_bfloat16 g_wl[(size_t)HH*HH];

// -------- per-batch-group grid barrier (monotonic, 4 domains of 32 CTAs) ---
__device__ unsigned g_cnt4[4*64];
__device__ unsigned g_gen4[4*64];

__device__ __forceinline__ unsigned ld_relaxed(const unsigned* p) {
    unsigned v;
    asm volatile("ld.relaxed.gpu.global.u32 %0, [%1];" : "=r"(v) : "l"(p) : "memory");
    return v;
}

__device__ __forceinline__ void group_sync(unsigned* cnt, unsigned* gen,
                                           unsigned target) {
    __syncthreads();
    if (threadIdx.x == 0) {
        unsigned old;
        asm volatile("atom.acq_rel.gpu.global.add.u32 %0, [%1], 1;"
                     : "=r"(old) : "l"(cnt) : "memory");
        if (old + 1u == 32u * target) {
            asm volatile("st.release.gpu.global.u32 [%0], %1;"
                         :: "l"(gen), "r"(target) : "memory");
        }
        unsigned v;
        do {
            asm volatile("ld.acquire.gpu.global.u32 %0, [%1];"
                         : "=r"(v) : "l"(gen) : "memory");
        } while ((int)(v - target) < 0);
    }
    __syncthreads();
}

// ---------------- bf16 split helpers ----------------
__device__ __forceinline__ uint packbf(float a, float b) {   // lo16=a, hi16=b
    uint r;
    asm("cvt.rn.bf16x2.f32 %0, %1, %2;" : "=r"(r) : "f"(b), "f"(a));
    return r;
}
__device__ __forceinline__ uint packlo(float a, float b, uint h) {
    float ha = __uint_as_float(h << 16);
    float hb = __uint_as_float(h & 0xFFFF0000u);
    return packbf(a - ha, b - hb);
}

// fp32 -> (bf16 hi, bf16 lo), 8 elements/thread
__global__ __launch_bounds__(256) void cvt_split_kernel(
    const float4* __restrict__ src, uint4* __restrict__ hi,
    uint4* __restrict__ lo, int n8)
{
    int i = blockIdx.x * 256 + threadIdx.x;
    if (i >= n8) return;
    float4 v0 = src[2*i], v1 = src[2*i + 1];
    uint h0 = packbf(v0.x, v0.y), h1 = packbf(v0.z, v0.w);
    uint h2 = packbf(v1.x, v1.y), h3 = packbf(v1.z, v1.w);
    uint l0 = packlo(v0.x, v0.y, h0), l1 = packlo(v0.z, v0.w, h1);
    uint l2 = packlo(v1.x, v1.y, h2), l3 = packlo(v1.z, v1.w, h3);
    hi[i] = make_uint4(h0, h1, h2, h3);
    lo[i] = make_uint4(l0, l1, l2, l3);
}

// ---------------- shared mma plumbing ----------------
__device__ __forceinline__ uint smem_u32(const void* p) {
    uint a;
    asm("{ .reg .u64 t; cvta.to.shared.u64 t, %1; cvt.u32.u64 %0, t; }"
        : "=r"(a) : "l"(p));
    return a;
}

#define LDSM4(r, addr) \
    asm volatile("ldmatrix.sync.aligned.m8n8.x4.shared.b16 {%0,%1,%2,%3}, [%4];" \
        : "=r"((r)[0]), "=r"((r)[1]), "=r"((r)[2]), "=r"((r)[3]) : "r"(addr))

#define MMA16816(d, a, b0, b1v) \
    asm volatile("mma.sync.aligned.m16n8k16.row.col.f32.bf16.bf16.f32 " \
        "{%0,%1,%2,%3}, {%4,%5,%6,%7}, {%8,%9}, {%0,%1,%2,%3};" \
        : "+f"((d)[0]), "+f"((d)[1]), "+f"((d)[2]), "+f"((d)[3]) \
        : "r"((a)[0]), "r"((a)[1]), "r"((a)[2]), "r"((a)[3]), "r"(b0), "r"(b1v))

#define STS128U(addr, a, b, c, d) \
    asm volatile("st.shared.v4.b32 [%0], {%1, %2, %3, %4};" \
                 :: "r"(addr), "r"(a), "r"(b), "r"(c), "r"(d) : "memory")

#define CPASYNC16(saddr, gptr) \
    asm volatile("cp.async.cg.shared.global [%0], [%1], 16;" \
                 :: "r"((uint)(saddr)), "l"(gptr) : "memory")
#define CPCOMMIT() asm volatile("cp.async.commit_group;" ::: "memory")
#define CPWAIT1()  asm volatile("cp.async.wait_group 1;" ::: "memory")
#define CPWAIT0()  asm volatile("cp.async.wait_group 0;" ::: "memory")

// ---------------- mma.sync bf16x3 GEMM, cp.async 3-stage (UNCHANGED) -------
#define GSTR 40
#define TBLK (128*GSTR)
#define TBLKB (TBLK*2)
#define NSTAGE 3
#define GEMM_SMEM (NSTAGE*4*TBLKB)     // 122880 B

__global__ __launch_bounds__(256) void mma_gemm_kernel(
    const __nv_bfloat16* __restrict__ Ah, const __nv_bfloat16* __restrict__ Al,
    const __nv_bfloat16* __restrict__ Wh, const __nv_bfloat16* __restrict__ Wl,
    const float* __restrict__ b1, const float* __restrict__ b2,
    float* __restrict__ out, int N, int K)
{
    extern __shared__ char gsm[];
    const uint sbase = smem_u32(gsm);
    const int tid  = threadIdx.x;
    const int warp = tid >> 5;
    const int lane = tid & 31;
    const int c0 = blockIdx.x * 128;
    const int r0 = blockIdx.y * 128;
    const int wm = warp >> 2;
    const int wn = warp & 3;

    const int lr = tid & 127;
    const __nv_bfloat16* gh0 = (tid < 128) ? (Ah + (size_t)(r0 + lr) * K)
                                           : (Wh + (size_t)(c0 + lr) * K);
    const __nv_bfloat16* gl0 = (tid < 128) ? (Al + (size_t)(r0 + lr) * K)
                                           : (Wl + (size_t)(c0 + lr) * K);
    const uint sdst_h = (tid < 128 ? 0u : 2u*TBLKB) + (uint)lr * (GSTR*2);

    const uint aoff = (((lane & 7) + ((lane >> 3) & 1) * 8) * GSTR
                       + (lane >> 4) * 8) * 2;
    const uint boff = (((lane & 7) + (lane >> 4) * 8) * GSTR
                       + ((lane >> 3) & 1) * 8) * 2;

    float acc[4][4][4];
    #pragma unroll
    for (int m = 0; m < 4; m++)
        #pragma unroll
        for (int n = 0; n < 4; n++)
            #pragma unroll
            for (int q = 0; q < 4; q++) acc[m][n][q] = 0.f;

    const int nk = K / 32;

    auto loadStageAsync = [&](int kt, int s) {
        const __nv_bfloat16* gh = gh0 + kt * 32;
        const __nv_bfloat16* gl = gl0 + kt * 32;
        uint bh = sbase + (uint)s * (4*TBLKB) + sdst_h;
        uint bl = bh + TBLKB;
        CPASYNC16(bh +  0, gh);
        CPASYNC16(bh + 16, gh + 8);
        CPASYNC16(bh + 32, gh + 16);
        CPASYNC16(bh + 48, gh + 24);
        CPASYNC16(bl +  0, gl);
        CPASYNC16(bl + 16, gl + 8);
        CPASYNC16(bl + 32, gl + 16);
        CPASYNC16(bl + 48, gl + 24);
        CPCOMMIT();
    };

    loadStageAsync(0, 0);
    loadStageAsync(1, 1);

    for (int kt = 0; kt < nk; kt++) {
        const int s = kt % NSTAGE;
        if (kt + 1 < nk) { CPWAIT1(); } else { CPWAIT0(); }
        __syncthreads();
        if (kt + 2 < nk) loadStageAsync(kt + 2, (kt + 2) % NSTAGE);

        const uint sb = sbase + (uint)s * (4*TBLKB);
        #pragma unroll
        for (int kb = 0; kb < 2; kb++) {
            const uint kbb = (uint)kb * 32;
            uint ah[4][4], al[4][4], bhf[2][4], blf[2][4];
            #pragma unroll
            for (int mt = 0; mt < 4; mt++) {
                uint ab = sb + ((uint)(wm*64 + mt*16) * GSTR) * 2 + kbb + aoff;
                LDSM4(ah[mt], ab);
                LDSM4(al[mt], ab + TBLKB);
            }
            #pragma unroll
            for (int nt2 = 0; nt2 < 2; nt2++) {
                uint bb = sb + 2u*TBLKB
                        + ((uint)(wn*32 + nt2*16) * GSTR) * 2 + kbb + boff;
                LDSM4(bhf[nt2], bb);
                LDSM4(blf[nt2], bb + TBLKB);
            }
            #pragma unroll
            for (int mt = 0; mt < 4; mt++)
                #pragma unroll
                for (int nt = 0; nt < 4; nt++) {
                    uint* bp = bhf[nt >> 1];
                    MMA16816(acc[mt][nt], ah[mt], bp[(nt & 1) * 2], bp[(nt & 1) * 2 + 1]);
                }
            #pragma unroll
            for (int mt = 0; mt < 4; mt++)
                #pragma unroll
                for (int nt = 0; nt < 4; nt++) {
                    uint* bp = blf[nt >> 1];
                    MMA16816(acc[mt][nt], ah[mt], bp[(nt & 1) * 2], bp[(nt & 1) * 2 + 1]);
                }
            #pragma unroll
            for (int mt = 0; mt < 4; mt++)
                #pragma unroll
                for (int nt = 0; nt < 4; nt++) {
                    uint* bp = bhf[nt >> 1];
                    MMA16816(acc[mt][nt], al[mt], bp[(nt & 1) * 2], bp[(nt & 1) * 2 + 1]);
                }
        }
    }

    const int rowb = r0 + wm*64 + (lane >> 2);
    const int colb = c0 + wn*32 + (lane & 3) * 2;
    #pragma unroll
    for (int nt = 0; nt < 4; nt++) {
        int col = colb + nt * 8;
        float bv0 = b1[col]     + (b2 ? b2[col]     : 0.f);
        float bv1 = b1[col + 1] + (b2 ? b2[col + 1] : 0.f);
        #pragma unroll
        for (int mt = 0; mt < 4; mt++) {
            int row = rowb + mt * 16;
            float2 o0 = make_float2(acc[mt][nt][0] + bv0, acc[mt][nt][1] + bv1);
            float2 o1 = make_float2(acc[mt][nt][2] + bv0, acc[mt][nt][3] + bv1);
            *(float2*)(out + (size_t)row * N + col)       = o0;
            *(float2*)(out + (size_t)(row + 8) * N + col) = o1;
        }
    }
}

// ------------- persistent recurrence, tensor-core + register-W -------------
// Exact r13 kernel + kt-parity 2-chain accumulator (same load order, +4 regs)
// + skip the final (intra-kernel-unneeded) barrier round.
__global__ __launch_bounds__(1024) void rnn_mma_kernel(
    const float* __restrict__ xw,
    __nv_bfloat16* __restrict__ yh, __nv_bfloat16* __restrict__ yl,
    float* __restrict__ yfp, const float* __restrict__ Whh, int nsteps)
{
    extern __shared__ char smemc[];
    const uint hbase = smem_u32(smemc);
    float* redf = (float*)(smemc + RED_OFF);   // [28 warps][32 lanes][4]

    const int tid = threadIdx.x;
    const int bid = blockIdx.x;
    const int cg  = bid & 31;
    const int bg  = bid >> 5;
    const int c0  = cg * 32;
    const int warp = tid >> 5;
    const int lane = tid & 31;
    const int kg  = warp >> 2;       // k-split 0..7 (128 k each)
    const int nt  = warp & 3;        // n-tile 0..3 (8 cols each)

    unsigned* cnt = &g_cnt4[bg*64];
    unsigned* gen = &g_gen4[bg*64];
    unsigned gen0 = ld_relaxed(gen);

    // ---- one-time: W B-fragments into registers (bf16 hi/lo) ----
    const int nW = c0 + nt*8 + (lane >> 2);
    const int kW = kg*128 + 2*(lane & 3);
    uint whi0[8], whi1[8], wlo0[8], wlo1[8];
    #pragma unroll
    for (int kt = 0; kt < 8; kt++) {
        const float* wp = Whh + (size_t)nW * HH + kW + kt*16;
        float2 w0 = *(const float2*)(wp);
        float2 w1 = *(const float2*)(wp + 8);
        whi0[kt] = packbf(w0.x, w0.y); wlo0[kt] = packlo(w0.x, w0.y, whi0[kt]);
        whi1[kt] = packbf(w1.x, w1.y); wlo1[kt] = packlo(w1.x, w1.y, whi1[kt]);
    }

    // staging: thread -> 16 k of one batch row (hi + lo), via cp.async
    const int sb  = tid & 15;
    const int skc = tid >> 4;        // 0..63
    const uint sdst = hbase + (uint)sb * (HSTR*2) + (uint)skc * 32;

    // ldmatrix A offset
    const uint aoff = (uint)(((lane & 7) + ((lane >> 3) & 1) * 8) * (HSTR*2)
                             + (lane >> 4) * 16);

    // epilogue mapping (D-frag)
    const int erow = bg*16 + (lane >> 2);
    const int ecol = c0 + nt*8 + (lane & 3)*2;

    for (int t = 0; t < nsteps; t++) {
        // stage h (hi/lo bf16) from slot t  (issue ASAP after barrier)
        {
            const __nv_bfloat16* sh = yh + (size_t)t*BBHH
                                      + (size_t)(bg*16 + sb)*HH + skc*16;
            const __nv_bfloat16* sl = yl + (size_t)t*BBHH
                                      + (size_t)(bg*16 + sb)*HH + skc*16;
            CPASYNC16(sdst,      sh);
            CPASYNC16(sdst + 16, sh + 8);
            CPASYNC16(sdst + HS_BYTES,      sl);
            CPASYNC16(sdst + HS_BYTES + 16, sl + 8);
            CPCOMMIT();
        }

        // prefetch xw for epilogue (reducing warps only)
        size_t idx0 = ((size_t)t*BB + erow)*HH + ecol;
        float2 xw0, xw8;
        if (kg == 0) {
            xw0 = *(const float2*)&xw[idx0];
            xw8 = *(const float2*)&xw[idx0 + 8*HH];
        }

        CPWAIT0();
        __syncthreads();

        // two accumulator chains by kt parity (load order identical to r13)
        float acc0[4] = {0.f, 0.f, 0.f, 0.f};
        float acc1[4] = {0.f, 0.f, 0.f, 0.f};
        #pragma unroll
        for (int kt = 0; kt < 8; kt++) {
            float* acc = (kt & 1) ? acc1 : acc0;
            uint ab = hbase + (uint)((kg*128 + kt*16) * 2) + aoff;
            uint Ah[4], Al[4];
            LDSM4(Ah, ab);
            MMA16816(acc, Ah, whi0[kt], whi1[kt]);   // Ah*Wh
            MMA16816(acc, Ah, wlo0[kt], wlo1[kt]);   // Ah*Wl
            LDSM4(Al, ab + HS_BYTES);
            MMA16816(acc, Al, whi0[kt], whi1[kt]);   // Al*Wh
        }
        float acc[4];
        #pragma unroll
        for (int q = 0; q < 4; q++) acc[q] = acc0[q] + acc1[q];

        // k-split reduction via smem (warps kg>0 store; kg==0 reduces)
        if (kg) *(float4*)(redf + (warp - 4)*128 + lane*4) = *(float4*)acc;
        __syncthreads();
        if (kg == 0) {
            #pragma unroll
            for (int k = 1; k < 8; k++) {
                float4 o = *(float4*)(redf + (k*4 + nt - 4)*128 + lane*4);
                acc[0] += o.x; acc[1] += o.y; acc[2] += o.z; acc[3] += o.w;
            }
            float t0 = tanhf(xw0.x + acc[0]);
            float t1 = tanhf(xw0.y + acc[1]);
            float t2 = tanhf(xw8.x + acc[2]);
            float t3 = tanhf(xw8.y + acc[3]);
            uint h01 = packbf(t0, t1), l01 = packlo(t0, t1, h01);
            uint h23 = packbf(t2, t3), l23 = packlo(t2, t3, h23);
            size_t o0 = idx0 + BBHH;          // slot t+1
            *(uint*)&yh[o0]          = h01;
            *(uint*)&yl[o0]          = l01;
            *(uint*)&yh[o0 + 8*HH]   = h23;
            *(uint*)&yl[o0 + 8*HH]   = l23;
            if (t == nsteps - 1) {
                *(float2*)&yfp[idx0]          = make_float2(t0, t1);
                *(float2*)&yfp[idx0 + 8*HH]   = make_float2(t2, t3);
            }
        }

        // final round's barrier is unneeded (cross-kernel ordering via stream);
        // skipping a full round preserves the cnt == 32*gen invariant.
        if (t + 1 < nsteps)
            group_sync(cnt, gen, gen0 + (unsigned)t + 1u);
    }
}

// ------------- hidden-state gather ----------------
__global__ void gather_hidden_kernel(float* __restrict__ out_hidden)
{
    int i = blockIdx.x * blockDim.x + threadIdx.x;
    const float* src = (i < BBHH)
        ? (g_y0 + (size_t)(TT-1)*BBHH + i)
        : (g_y1 + (size_t)(TT-1)*BBHH + (i - BBHH));
    out_hidden[i] = *src;
}

extern "C" void kernel_launch(void* const* d_in, const int* in_sizes, int n_in,
                              void* d_out, int out_size) {
    const float* x     = (const float*)d_in[0];
    const float* h0    = (const float*)d_in[1];
    const float* w_ih0 = (const float*)d_in[2];
    const float* w_hh0 = (const float*)d_in[3];
    const float* b_ih0 = (const float*)d_in[4];
    const float* b_hh0 = (const float*)d_in[5];
    const float* w_ih1 = (const float*)d_in[6];
    const float* w_hh1 = (const float*)d_in[7];
    const float* b_ih1 = (const float*)d_in[8];
    const float* b_hh1 = (const float*)d_in[9];
    const float* w_dec = (const float*)d_in[10];
    const float* b_dec = (const float*)d_in[11];
    float* out = (float*)d_out;

    cudaFuncSetAttribute(rnn_mma_kernel,
                         cudaFuncAttributeMaxDynamicSharedMemorySize, RNN2_SMEM);
    cudaFuncSetAttribute(mma_gemm_kernel,
                         cudaFuncAttributeMaxDynamicSharedMemorySize, GEMM_SMEM);

    float* xw;  cudaGetSymbolAddress((void**)&xw,  g_xw);
    float* y0;  cudaGetSymbolAddress((void**)&y0,  g_y0);
    float* y1;  cudaGetSymbolAddress((void**)&y1,  g_y1);
    __nv_bfloat16 *ah, *al, *wh, *wl, *y0h, *y0l, *y1h, *y1l;
    cudaGetSymbolAddress((void**)&ah,  g_ah);
    cudaGetSymbolAddress((void**)&al,  g_al);
    cudaGetSymbolAddress((void**)&wh,  g_wh);
    cudaGetSymbolAddress((void**)&wl,  g_wl);
    cudaGetSymbolAddress((void**)&y0h, g_y0h);
    cudaGetSymbolAddress((void**)&y0l, g_y0l);
    cudaGetSymbolAddress((void**)&y1h, g_y1h);
    cudaGetSymbolAddress((void**)&y1l, g_y1l);

    // 0) split x, w_ih0, and both h0 slices (h0 -> slot 0 of yh/yl arrays)
    cvt_split_kernel<<<RR*CC/8/256, 256>>>((const float4*)x, (uint4*)ah, (uint4*)al, RR*CC/8);
    cvt_split_kernel<<<HH*CC/8/256, 256>>>((const float4*)w_ih0, (uint4*)wh, (uint4*)wl, HH*CC/8);
    cvt_split_kernel<<<BBHH/8/256, 256>>>((const float4*)h0, (uint4*)y0h, (uint4*)y0l, BBHH/8);
    cvt_split_kernel<<<BBHH/8/256, 256>>>((const float4*)(h0 + BBHH), (uint4*)y1h, (uint4*)y1l, BBHH/8);

    // 1) layer-0 input projection: xw = x @ w_ih0^T + b_ih0 + b_hh0
    {
        dim3 grid(HH/128, RR/128);
        mma_gemm_kernel<<<grid, 256, GEMM_SMEM>>>(ah, al, wh, wl, b_ih0, b_hh0, xw, HH, CC);
    }
    // 2) layer-0 recurrence
    rnn_mma_kernel<<<NB_RNN, 1024, RNN2_SMEM>>>(xw, y0h, y0l, y0, w_hh0, TT);
    // 3) layer-1 input projection (A = y0 hi/lo slots 1..512 directly)
    cvt_split_kernel<<<HH*HH/8/256, 256>>>((const float4*)w_ih1, (uint4*)wh, (uint4*)wl, HH*HH/8);
    {
        dim3 grid(HH/128, RR/128);
        mma_gemm_kernel<<<grid, 256, GEMM_SMEM>>>(y0h + BBHH, y0l + BBHH, wh, wl,
                                                  b_ih1, b_hh1, xw, HH, HH);
    }
    // 4) layer-1 recurrence
    rnn_mma_kernel<<<NB_RNN, 1024, RNN2_SMEM>>>(xw, y1h, y1l, y1, w_hh1, TT);
    // 5) decoder (A = y1 hi/lo slots 1..512)
    cvt_split_kernel<<<CC*HH/8/256, 256>>>((const float4*)w_dec, (uint4*)wh, (uint4*)wl, CC*HH/8);
    {
        dim3 grid(CC/128, RR/128);
        mma_gemm_kernel<<<grid, 256, GEMM_SMEM>>>(y1h + BBHH, y1l + BBHH, wh, wl,
                                                  b_dec, nullptr, out, CC, HH);
    }
    // 6) hidden states appended after decoded
    gather_hidden_kernel<<<(2*BBHH)/256, 256>>>(out + (size_t)TT*BB*CC);
}

// round 17
// speedup vs baseline: 2.1586x; 1.0608x over previous
#include <cuda_runtime.h>
#include <cuda_bf16.h>
#include <math.h>

#define TT 512
#define BB 64
#define CC 256
#define HH 1024
#define RR (TT*BB)
#define BBHH (BB*HH)

#define NB_RNN 128
#define HSTR 1032                         // bf16 row stride (2064 B)
#define HS_BYTES (16*HSTR*2)              // one h buffer (hi or lo): 33024
#define RED_OFF (2*HS_BYTES)              // 66048
#define RNN2_SMEM (RED_OFF + 28*32*16)    // + red 14336 = 80384

typedef unsigned long long ull;
typedef unsigned int uint;

// ---------------- scratch ----------------
__device__ float g_xw[(size_t)TT*BB*HH];
__device__ float g_y0[(size_t)TT*BB*HH];
__device__ float g_y1[(size_t)TT*BB*HH];
// bf16 hi/lo activation arrays; slot 0 = initial h, slot t+1 = y[t]
__device__ __nv_bfloat16 g_y0h[(size_t)(TT+1)*BBHH];
__device__ __nv_bfloat16 g_y0l[(size_t)(TT+1)*BBHH];
__device__ __nv_bfloat16 g_y1h[(size_t)(TT+1)*BBHH];
__device__ __nv_bfloat16 g_y1l[(size_t)(TT+1)*BBHH];
// bf16 split scratch for GEMM inputs (x) and weights
__device__ __nv_bfloat16 g_ah[(size_t)RR*CC];
__device__ __nv_bfloat16 g_al[(size_t)RR*CC];
__device__ __nv_bfloat16 g_wh[(size_t)HH*HH];
__device__ __nv_bfloat16 g_wl[(size_t)HH*HH];

// -------- per-batch-group grid barrier (monotonic, 4 domains of 32 CTAs) ---
__device__ unsigned g_cnt4[4*64];
__device__ unsigned g_gen4[4*64];

__device__ __forceinline__ unsigned ld_relaxed(const unsigned* p) {
    unsigned v;
    asm volatile("ld.relaxed.gpu.global.u32 %0, [%1];" : "=r"(v) : "l"(p) : "memory");
    return v;
}

__device__ __forceinline__ void group_sync(unsigned* cnt, unsigned* gen,
                                           unsigned target) {
    __syncthreads();
    if (threadIdx.x == 0) {
        unsigned old;
        asm volatile("atom.acq_rel.gpu.global.add.u32 %0, [%1], 1;"
                     : "=r"(old) : "l"(cnt) : "memory");
        if (old + 1u == 32u * target) {
            asm volatile("st.release.gpu.global.u32 [%0], %1;"
                         :: "l"(gen), "r"(target) : "memory");
        }
        unsigned v;
        do {
            asm volatile("ld.acquire.gpu.global.u32 %0, [%1];"
                         : "=r"(v) : "l"(gen) : "memory");
        } while ((int)(v - target) < 0);
    }
    __syncthreads();
}

// ---------------- bf16 split helpers ----------------
__device__ __forceinline__ uint packbf(float a, float b) {   // lo16=a, hi16=b
    uint r;
    asm("cvt.rn.bf16x2.f32 %0, %1, %2;" : "=r"(r) : "f"(b), "f"(a));
    return r;
}
__device__ __forceinline__ uint packlo(float a, float b, uint h) {
    float ha = __uint_as_float(h << 16);
    float hb = __uint_as_float(h & 0xFFFF0000u);
    return packbf(a - ha, b - hb);
}

// fp32 -> (bf16 hi, bf16 lo), 8 elements/thread
__global__ __launch_bounds__(256) void cvt_split_kernel(
    const float4* __restrict__ src, uint4* __restrict__ hi,
    uint4* __restrict__ lo, int n8)
{
    int i = blockIdx.x * 256 + threadIdx.x;
    if (i >= n8) return;
    float4 v0 = src[2*i], v1 = src[2*i + 1];
    uint h0 = packbf(v0.x, v0.y), h1 = packbf(v0.z, v0.w);
    uint h2 = packbf(v1.x, v1.y), h3 = packbf(v1.z, v1.w);
    uint l0 = packlo(v0.x, v0.y, h0), l1 = packlo(v0.z, v0.w, h1);
    uint l2 = packlo(v1.x, v1.y, h2), l3 = packlo(v1.z, v1.w, h3);
    hi[i] = make_uint4(h0, h1, h2, h3);
    lo[i] = make_uint4(l0, l1, l2, l3);
}

// ---------------- shared mma plumbing ----------------
__device__ __forceinline__ uint smem_u32(const void* p) {
    uint a;
    asm("{ .reg .u64 t; cvta.to.shared.u64 t, %1; cvt.u32.u64 %0, t; }"
        : "=r"(a) : "l"(p));
    return a;
}

#define LDSM4(r, addr) \
    asm volatile("ldmatrix.sync.aligned.m8n8.x4.shared.b16 {%0,%1,%2,%3}, [%4];" \
        : "=r"((r)[0]), "=r"((r)[1]), "=r"((r)[2]), "=r"((r)[3]) : "r"(addr))

#define MMA16816(d, a, b0, b1v) \
    asm volatile("mma.sync.aligned.m16n8k16.row.col.f32.bf16.bf16.f32 " \
        "{%0,%1,%2,%3}, {%4,%5,%6,%7}, {%8,%9}, {%0,%1,%2,%3};" \
        : "+f"((d)[0]), "+f"((d)[1]), "+f"((d)[2]), "+f"((d)[3]) \
        : "r"((a)[0]), "r"((a)[1]), "r"((a)[2]), "r"((a)[3]), "r"(b0), "r"(b1v))

#define STS128U(addr, a, b, c, d) \
    asm volatile("st.shared.v4.b32 [%0], {%1, %2, %3, %4};" \
                 :: "r"(addr), "r"(a), "r"(b), "r"(c), "r"(d) : "memory")

#define CPASYNC16(saddr, gptr) \
    asm volatile("cp.async.cg.shared.global [%0], [%1], 16;" \
                 :: "r"((uint)(saddr)), "l"(gptr) : "memory")
#define CPCOMMIT() asm volatile("cp.async.commit_group;" ::: "memory")
#define CPWAIT1()  asm volatile("cp.async.wait_group 1;" ::: "memory")
#define CPWAIT0()  asm volatile("cp.async.wait_group 0;" ::: "memory")

// ---------------- mma.sync bf16x3 GEMM, cp.async 3-stage (UNCHANGED) -------
#define GSTR 40
#define TBLK (128*GSTR)
#define TBLKB (TBLK*2)
#define NSTAGE 3
#define GEMM_SMEM (NSTAGE*4*TBLKB)     // 122880 B

__global__ __launch_bounds__(256) void mma_gemm_kernel(
    const __nv_bfloat16* __restrict__ Ah, const __nv_bfloat16* __restrict__ Al,
    const __nv_bfloat16* __restrict__ Wh, const __nv_bfloat16* __restrict__ Wl,
    const float* __restrict__ b1, const float* __restrict__ b2,
    float* __restrict__ out, int N, int K)
{
    extern __shared__ char gsm[];
    const uint sbase = smem_u32(gsm);
    const int tid  = threadIdx.x;
    const int warp = tid >> 5;
    const int lane = tid & 31;
    const int c0 = blockIdx.x * 128;
    const int r0 = blockIdx.y * 128;
    const int wm = warp >> 2;
    const int wn = warp & 3;

    const int lr = tid & 127;
    const __nv_bfloat16* gh0 = (tid < 128) ? (Ah + (size_t)(r0 + lr) * K)
                                           : (Wh + (size_t)(c0 + lr) * K);
    const __nv_bfloat16* gl0 = (tid < 128) ? (Al + (size_t)(r0 + lr) * K)
                                           : (Wl + (size_t)(c0 + lr) * K);
    const uint sdst_h = (tid < 128 ? 0u : 2u*TBLKB) + (uint)lr * (GSTR*2);

    const uint aoff = (((lane & 7) + ((lane >> 3) & 1) * 8) * GSTR
                       + (lane >> 4) * 8) * 2;
    const uint boff = (((lane & 7) + (lane >> 4) * 8) * GSTR
                       + ((lane >> 3) & 1) * 8) * 2;

    float acc[4][4][4];
    #pragma unroll
    for (int m = 0; m < 4; m++)
        #pragma unroll
        for (int n = 0; n < 4; n++)
            #pragma unroll
            for (int q = 0; q < 4; q++) acc[m][n][q] = 0.f;

    const int nk = K / 32;

    auto loadStageAsync = [&](int kt, int s) {
        const __nv_bfloat16* gh = gh0 + kt * 32;
        const __nv_bfloat16* gl = gl0 + kt * 32;
        uint bh = sbase + (uint)s * (4*TBLKB) + sdst_h;
        uint bl = bh + TBLKB;
        CPASYNC16(bh +  0, gh);
        CPASYNC16(bh + 16, gh + 8);
        CPASYNC16(bh + 32, gh + 16);
        CPASYNC16(bh + 48, gh + 24);
        CPASYNC16(bl +  0, gl);
        CPASYNC16(bl + 16, gl + 8);
        CPASYNC16(bl + 32, gl + 16);
        CPASYNC16(bl + 48, gl + 24);
        CPCOMMIT();
    };

    loadStageAsync(0, 0);
    loadStageAsync(1, 1);

    for (int kt = 0; kt < nk; kt++) {
        const int s = kt % NSTAGE;
        if (kt + 1 < nk) { CPWAIT1(); } else { CPWAIT0(); }
        __syncthreads();
        if (kt + 2 < nk) loadStageAsync(kt + 2, (kt + 2) % NSTAGE);

        const uint sb = sbase + (uint)s * (4*TBLKB);
        #pragma unroll
        for (int kb = 0; kb < 2; kb++) {
            const uint kbb = (uint)kb * 32;
            uint ah[4][4], al[4][4], bhf[2][4], blf[2][4];
            #pragma unroll
            for (int mt = 0; mt < 4; mt++) {
                uint ab = sb + ((uint)(wm*64 + mt*16) * GSTR) * 2 + kbb + aoff;
                LDSM4(ah[mt], ab);
                LDSM4(al[mt], ab + TBLKB);
            }
            #pragma unroll
            for (int nt2 = 0; nt2 < 2; nt2++) {
                uint bb = sb + 2u*TBLKB
                        + ((uint)(wn*32 + nt2*16) * GSTR) * 2 + kbb + boff;
                LDSM4(bhf[nt2], bb);
                LDSM4(blf[nt2], bb + TBLKB);
            }
            #pragma unroll
            for (int mt = 0; mt < 4; mt++)
                #pragma unroll
                for (int nt = 0; nt < 4; nt++) {
                    uint* bp = bhf[nt >> 1];
                    MMA16816(acc[mt][nt], ah[mt], bp[(nt & 1) * 2], bp[(nt & 1) * 2 + 1]);
                }
            #pragma unroll
            for (int mt = 0; mt < 4; mt++)
                #pragma unroll
                for (int nt = 0; nt < 4; nt++) {
                    uint* bp = blf[nt >> 1];
                    MMA16816(acc[mt][nt], ah[mt], bp[(nt & 1) * 2], bp[(nt & 1) * 2 + 1]);
                }
            #pragma unroll
            for (int mt = 0; mt < 4; mt++)
                #pragma unroll
                for (int nt = 0; nt < 4; nt++) {
                    uint* bp = bhf[nt >> 1];
                    MMA16816(acc[mt][nt], al[mt], bp[(nt & 1) * 2], bp[(nt & 1) * 2 + 1]);
                }
        }
    }

    const int rowb = r0 + wm*64 + (lane >> 2);
    const int colb = c0 + wn*32 + (lane & 3) * 2;
    #pragma unroll
    for (int nt = 0; nt < 4; nt++) {
        int col = colb + nt * 8;
        float bv0 = b1[col]     + (b2 ? b2[col]     : 0.f);
        float bv1 = b1[col + 1] + (b2 ? b2[col + 1] : 0.f);
        #pragma unroll
        for (int mt = 0; mt < 4; mt++) {
            int row = rowb + mt * 16;
            float2 o0 = make_float2(acc[mt][nt][0] + bv0, acc[mt][nt][1] + bv1);
            float2 o1 = make_float2(acc[mt][nt][2] + bv0, acc[mt][nt][3] + bv1);
            *(float2*)(out + (size_t)row * N + col)       = o0;
            *(float2*)(out + (size_t)(row + 8) * N + col) = o1;
        }
    }
}

// ------------- persistent recurrence, tensor-core + register-W -------------
// Exact r13 kernel (single acc chain) with two deltas:
//  (1) pre-compute CTA-wide __syncthreads -> per-kg-group named barrier
//      (group kg stages exactly the k-slice only it consumes)
//  (2) final barrier round skipped (stream ordering covers cross-kernel vis.)
__global__ __launch_bounds__(1024) void rnn_mma_kernel(
    const float* __restrict__ xw,
    __nv_bfloat16* __restrict__ yh, __nv_bfloat16* __restrict__ yl,
    float* __restrict__ yfp, const float* __restrict__ Whh, int nsteps)
{
    extern __shared__ char smemc[];
    const uint hbase = smem_u32(smemc);
    float* redf = (float*)(smemc + RED_OFF);   // [28 warps][32 lanes][4]

    const int tid = threadIdx.x;
    const int bid = blockIdx.x;
    const int cg  = bid & 31;
    const int bg  = bid >> 5;
    const int c0  = cg * 32;
    const int warp = tid >> 5;
    const int lane = tid & 31;
    const int kg  = warp >> 2;       // k-split 0..7 (128 k each)
    const int nt  = warp & 3;        // n-tile 0..3 (8 cols each)

    unsigned* cnt = &g_cnt4[bg*64];
    unsigned* gen = &g_gen4[bg*64];
    unsigned gen0 = ld_relaxed(gen);

    // ---- one-time: W B-fragments into registers (bf16 hi/lo) ----
    const int nW = c0 + nt*8 + (lane >> 2);
    const int kW = kg*128 + 2*(lane & 3);
    uint whi0[8], whi1[8], wlo0[8], wlo1[8];
    #pragma unroll
    for (int kt = 0; kt < 8; kt++) {
        const float* wp = Whh + (size_t)nW * HH + kW + kt*16;
        float2 w0 = *(const float2*)(wp);
        float2 w1 = *(const float2*)(wp + 8);
        whi0[kt] = packbf(w0.x, w0.y); wlo0[kt] = packlo(w0.x, w0.y, whi0[kt]);
        whi1[kt] = packbf(w1.x, w1.y); wlo1[kt] = packlo(w1.x, w1.y, whi1[kt]);
    }

    // staging: thread -> 16 k of one batch row (hi + lo), via cp.async.
    // Threads of warp-group kg (tids 128kg..128kg+127) stage exactly
    // k-slice [128kg, 128(kg+1)) -- the slice only group kg consumes.
    const int sb  = tid & 15;
    const int skc = tid >> 4;        // 0..63
    const uint sdst = hbase + (uint)sb * (HSTR*2) + (uint)skc * 32;

    // ldmatrix A offset
    const uint aoff = (uint)(((lane & 7) + ((lane >> 3) & 1) * 8) * (HSTR*2)
                             + (lane >> 4) * 16);

    // epilogue mapping (D-frag)
    const int erow = bg*16 + (lane >> 2);
    const int ecol = c0 + nt*8 + (lane & 3)*2;

    for (int t = 0; t < nsteps; t++) {
        // stage h (hi/lo bf16) from slot t  (issue ASAP after barrier)
        {
            const __nv_bfloat16* sh = yh + (size_t)t*BBHH
                                      + (size_t)(bg*16 + sb)*HH + skc*16;
            const __nv_bfloat16* sl = yl + (size_t)t*BBHH
                                      + (size_t)(bg*16 + sb)*HH + skc*16;
            CPASYNC16(sdst,      sh);
            CPASYNC16(sdst + 16, sh + 8);
            CPASYNC16(sdst + HS_BYTES,      sl);
            CPASYNC16(sdst + HS_BYTES + 16, sl + 8);
            CPCOMMIT();
        }

        // prefetch xw for epilogue (reducing warps only)
        size_t idx0 = ((size_t)t*BB + erow)*HH + ecol;
        float2 xw0, xw8;
        if (kg == 0) {
            xw0 = *(const float2*)&xw[idx0];
            xw8 = *(const float2*)&xw[idx0 + 8*HH];
        }

        CPWAIT0();
        // group-local barrier: only the 4 warps of group kg must agree
        // (they staged the slice they consume). Frees early groups to run.
        asm volatile("bar.sync %0, 128;" :: "r"(kg + 1) : "memory");

        // single accumulator chain (r13-proven loop body)
        float acc[4] = {0.f, 0.f, 0.f, 0.f};
        #pragma unroll
        for (int kt = 0; kt < 8; kt++) {
            uint ab = hbase + (uint)((kg*128 + kt*16) * 2) + aoff;
            uint Ah[4], Al[4];
            LDSM4(Ah, ab);
            MMA16816(acc, Ah, whi0[kt], whi1[kt]);   // Ah*Wh
            MMA16816(acc, Ah, wlo0[kt], wlo1[kt]);   // Ah*Wl
            LDSM4(Al, ab + HS_BYTES);
            MMA16816(acc, Al, whi0[kt], whi1[kt]);   // Al*Wh
        }

        // k-split reduction via smem (warps kg>0 store; kg==0 reduces)
        if (kg) *(float4*)(redf + (warp - 4)*128 + lane*4) = *(float4*)acc;
        __syncthreads();
        if (kg == 0) {
            #pragma unroll
            for (int k = 1; k < 8; k++) {
                float4 o = *(float4*)(redf + (k*4 + nt - 4)*128 + lane*4);
                acc[0] += o.x; acc[1] += o.y; acc[2] += o.z; acc[3] += o.w;
            }
            float t0 = tanhf(xw0.x + acc[0]);
            float t1 = tanhf(xw0.y + acc[1]);
            float t2 = tanhf(xw8.x + acc[2]);
            float t3 = tanhf(xw8.y + acc[3]);
            uint h01 = packbf(t0, t1), l01 = packlo(t0, t1, h01);
            uint h23 = packbf(t2, t3), l23 = packlo(t2, t3, h23);
            size_t o0 = idx0 + BBHH;          // slot t+1
            *(uint*)&yh[o0]          = h01;
            *(uint*)&yl[o0]          = l01;
            *(uint*)&yh[o0 + 8*HH]   = h23;
            *(uint*)&yl[o0 + 8*HH]   = l23;
            if (t == nsteps - 1) {
                *(float2*)&yfp[idx0]          = make_float2(t0, t1);
                *(float2*)&yfp[idx0 + 8*HH]   = make_float2(t2, t3);
            }
        }

        // final round's barrier unneeded; skipping a full round keeps
        // cnt == 32*gen consistent (both advance 511 per launch).
        if (t + 1 < nsteps)
            group_sync(cnt, gen, gen0 + (unsigned)t + 1u);
    }
}

// ------------- hidden-state gather ----------------
__global__ void gather_hidden_kernel(float* __restrict__ out_hidden)
{
    int i = blockIdx.x * blockDim.x + threadIdx.x;
    const float* src = (i < BBHH)
        ? (g_y0 + (size_t)(TT-1)*BBHH + i)
        : (g_y1 + (size_t)(TT-1)*BBHH + (i - BBHH));
    out_hidden[i] = *src;
}

extern "C" void kernel_launch(void* const* d_in, const int* in_sizes, int n_in,
                              void* d_out, int out_size) {
    const float* x     = (const float*)d_in[0];
    const float* h0    = (const float*)d_in[1];
    const float* w_ih0 = (const float*)d_in[2];
    const float* w_hh0 = (const float*)d_in[3];
    const float* b_ih0 = (const float*)d_in[4];
    const float* b_hh0 = (const float*)d_in[5];
    const float* w_ih1 = (const float*)d_in[6];
    const float* w_hh1 = (const float*)d_in[7];
    const float* b_ih1 = (const float*)d_in[8];
    const float* b_hh1 = (const float*)d_in[9];
    const float* w_dec = (const float*)d_in[10];
    const float* b_dec = (const float*)d_in[11];
    float* out = (float*)d_out;

    cudaFuncSetAttribute(rnn_mma_kernel,
                         cudaFuncAttributeMaxDynamicSharedMemorySize, RNN2_SMEM);
    cudaFuncSetAttribute(mma_gemm_kernel,
                         cudaFuncAttributeMaxDynamicSharedMemorySize, GEMM_SMEM);

    float* xw;  cudaGetSymbolAddress((void**)&xw,  g_xw);
    float* y0;  cudaGetSymbolAddress((void**)&y0,  g_y0);
    float* y1;  cudaGetSymbolAddress((void**)&y1,  g_y1);
    __nv_bfloat16 *ah, *al, *wh, *wl, *y0h, *y0l, *y1h, *y1l;
    cudaGetSymbolAddress((void**)&ah,  g_ah);
    cudaGetSymbolAddress((void**)&al,  g_al);
    cudaGetSymbolAddress((void**)&wh,  g_wh);
    cudaGetSymbolAddress((void**)&wl,  g_wl);
    cudaGetSymbolAddress((void**)&y0h, g_y0h);
    cudaGetSymbolAddress((void**)&y0l, g_y0l);
    cudaGetSymbolAddress((void**)&y1h, g_y1h);
    cudaGetSymbolAddress((void**)&y1l, g_y1l);

    // 0) split x, w_ih0, and both h0 slices (h0 -> slot 0 of yh/yl arrays)
    cvt_split_kernel<<<RR*CC/8/256, 256>>>((const float4*)x, (uint4*)ah, (uint4*)al, RR*CC/8);
    cvt_split_kernel<<<HH*CC/8/256, 256>>>((const float4*)w_ih0, (uint4*)wh, (uint4*)wl, HH*CC/8);
    cvt_split_kernel<<<BBHH/8/256, 256>>>((const float4*)h0, (uint4*)y0h, (uint4*)y0l, BBHH/8);
    cvt_split_kernel<<<BBHH/8/256, 256>>>((const float4*)(h0 + BBHH), (uint4*)y1h, (uint4*)y1l, BBHH/8);

    // 1) layer-0 input projection: xw = x @ w_ih0^T + b_ih0 + b_hh0
    {
        dim3 grid(HH/128, RR/128);
        mma_gemm_kernel<<<grid, 256, GEMM_SMEM>>>(ah, al, wh, wl, b_ih0, b_hh0, xw, HH, CC);
    }
    // 2) layer-0 recurrence
    rnn_mma_kernel<<<NB_RNN, 1024, RNN2_SMEM>>>(xw, y0h, y0l, y0, w_hh0, TT);
    // 3) layer-1 input projection (A = y0 hi/lo slots 1..512 directly)
    cvt_split_kernel<<<HH*HH/8/256, 256>>>((const float4*)w_ih1, (uint4*)wh, (uint4*)wl, HH*HH/8);
    {
        dim3 grid(HH/128, RR/128);
        mma_gemm_kernel<<<grid, 256, GEMM_SMEM>>>(y0h + BBHH, y0l + BBHH, wh, wl,
                                                  b_ih1, b_hh1, xw, HH, HH);
    }
    // 4) layer-1 recurrence
    rnn_mma_kernel<<<NB_RNN, 1024, RNN2_SMEM>>>(xw, y1h, y1l, y1, w_hh1, TT);
    // 5) decoder (A = y1 hi/lo slots 1..512)
    cvt_split_kernel<<<CC*HH/8/256, 256>>>((const float4*)w_dec, (uint4*)wh, (uint4*)wl, CC*HH/8);
    {
        dim3 grid(CC/128, RR/128);
        mma_gemm_kernel<<<grid, 256, GEMM_SMEM>>>(y1h + BBHH, y1l + BBHH, wh, wl,
                                                  b_dec, nullptr, out, CC, HH);
    }
    // 6) hidden states appended after decoded
    gather_hidden_kernel<<<(2*BBHH)/256, 256>>>(out + (size_t)TT*BB*CC);
}